// round 13
// baseline (speedup 1.0000x reference)
#include <cuda_runtime.h>
#include <cuda_bf16.h>
#include <cuda_fp16.h>
#include <math.h>

#define NN 100000
#define EE 500000
#define BB 8192
#define NBLK 391                     // ceil(NN/256)
#define NGB 782                      // gemm blocks per type (ceil(NN/128))
#define NHB 977                      // hist blocks per metapath (512 edges each)

// ---------------- scratch (device globals) ----------------------------------
__device__ __half g_feat_h[4][NN * 64];        // fp16 feat per slot
__device__ __half g_z_h[4][NN * 64];           // fp16 normalized GAT output
__device__ float g_el[4][NN];
__device__ float g_er[4][NN];
__device__ int   g_cnt[4][NN];                 // histogram (zero at call entry)
__device__ int   g_cur[4][NN];                 // scatter cursor
__device__ int   g_rowptr[4][NN + 1];
__device__ unsigned long long g_scan_st[4][NBLK];  // lookback state (zeroed by scatter)
__device__ __align__(16) unsigned long long g_csr[4][EE];  // (exp << 32) | src
__device__ float g_w[4];

// ---------------- helpers ----------------------------------------------------
__device__ __forceinline__ float tanh_fast(float x) {
    float y; asm("tanh.approx.f32 %0, %1;" : "=f"(y) : "f"(x)); return y;
}
__device__ __forceinline__ float elu_fast(float x) {
    return x > 0.f ? x : (__expf(x) - 1.f);
}
__device__ __forceinline__ unsigned int bf2(float lo, float hi) {
    __nv_bfloat162 v = __floats2bfloat162_rn(lo, hi);
    return *reinterpret_cast<unsigned int*>(&v);
}
__device__ __forceinline__ unsigned int to_tf32(float f) {
    unsigned int u; asm("cvt.rna.tf32.f32 %0, %1;" : "=r"(u) : "f"(f)); return u;
}
__device__ __forceinline__ void mma_bf16(
    float& c0, float& c1, float& c2, float& c3,
    unsigned int a0, unsigned int a1, unsigned int a2, unsigned int a3,
    unsigned int b0, unsigned int b1)
{
    asm("mma.sync.aligned.m16n8k16.row.col.f32.bf16.bf16.f32 "
        "{%0,%1,%2,%3}, {%4,%5,%6,%7}, {%8,%9}, {%0,%1,%2,%3};"
        : "+f"(c0), "+f"(c1), "+f"(c2), "+f"(c3)
        : "r"(a0), "r"(a1), "r"(a2), "r"(a3), "r"(b0), "r"(b1));
}
__device__ __forceinline__ void mma_tf32(
    float* c, unsigned int a0, unsigned int a1, unsigned int a2, unsigned int a3,
    unsigned int b0, unsigned int b1)
{
    asm("mma.sync.aligned.m16n8k8.row.col.f32.tf32.tf32.f32 "
        "{%0,%1,%2,%3}, {%4,%5,%6,%7}, {%8,%9}, {%0,%1,%2,%3};"
        : "+f"(c[0]), "+f"(c[1]), "+f"(c[2]), "+f"(c[3])
        : "r"(a0), "r"(a1), "r"(a2), "r"(a3), "r"(b0), "r"(b1));
}

// ---------------- K1: fused feat GEMM (both metapaths) + degree histogram ---
#define HS_STRIDE 68
#define K1F_SMEM ((128 * HS_STRIDE + 2 * 4096 + 512) * 4)

__global__ void __launch_bounds__(256) k_fused1(
    const float* __restrict__ h_u, const float* __restrict__ h_i,
    const float* __restrict__ W_u, const float* __restrict__ W_i,
    const float* __restrict__ al_u, const float* __restrict__ al_i,
    const float* __restrict__ ar_u, const float* __restrict__ ar_i,
    const int* __restrict__ u_dst, const int* __restrict__ i_dst)
{
    int type = blockIdx.y;
    int tid  = threadIdx.x;

    // ---- histogram role ----
    if (blockIdx.x >= NGB) {
        int hb = blockIdx.x - NGB;           // 0 .. 2*NHB-1
        int m  = hb >= NHB;
        int b  = hb - m * NHB;
        int slot = 2 * type + m;
        const int* dst = (type ? i_dst : u_dst) + (size_t)m * EE;
        int e0 = b * 512 + tid;
        if (e0 < EE) atomicAdd(&g_cnt[slot][dst[e0]], 1);
        int e1 = e0 + 256;
        if (e1 < EE) atomicAdd(&g_cnt[slot][dst[e1]], 1);
        return;
    }

    // ---- gemm role ----
    extern __shared__ unsigned int smemu[];
    unsigned int* hsU = smemu;                  // 128 x 68 (tf32 bits)
    unsigned int* WsU = hsU + 128 * HS_STRIDE;  // 2 x 64 x 64 (tf32 bits)
    float* el_s = (float*)(WsU + 2 * 4096);     // 2 x 128
    float* er_s = el_s + 256;                   // 2 x 128

    const float* h  = type ? h_i : h_u;
    const float* W  = type ? W_i : W_u;
    const float* al = type ? al_i : al_u;
    const float* ar = type ? ar_i : ar_u;

    int row0 = blockIdx.x * 128;

    if (blockIdx.x == 0 && type == 0 && tid < 4) g_w[tid] = 0.0f;

    for (int i = tid; i < 8192; i += 256) WsU[i] = to_tf32(W[i]);

    {
        int r  = tid >> 1;
        int kq = (tid & 1) * 32;
        int grow = row0 + r;
        unsigned int* dst = &hsU[r * HS_STRIDE + kq];
        if (grow < NN) {
            const float4* hp = (const float4*)&h[(size_t)grow * 64 + kq];
#pragma unroll
            for (int j = 0; j < 8; j++) {
                float4 v = hp[j];
                dst[4 * j + 0] = to_tf32(v.x);
                dst[4 * j + 1] = to_tf32(v.y);
                dst[4 * j + 2] = to_tf32(v.z);
                dst[4 * j + 3] = to_tf32(v.w);
            }
        } else {
#pragma unroll
            for (int j = 0; j < 32; j++) dst[j] = 0u;
        }
    }
    el_s[tid] = 0.0f;
    er_s[tid] = 0.0f;
    __syncthreads();

    int lane = tid & 31, warp = tid >> 5;
    int g = lane >> 2, tig = lane & 3;
    int mq = warp & 1, nq = warp >> 1;

#pragma unroll
    for (int m2 = 0; m2 < 2; m2++) {
        int slot = 2 * type + m2;
        const unsigned int* Wm = WsU + m2 * 4096;

        unsigned int bfr[8][2][2];
#pragma unroll
        for (int kt = 0; kt < 8; kt++)
#pragma unroll
            for (int nt = 0; nt < 2; nt++) {
                int n = nq * 16 + nt * 8 + g;
                bfr[kt][nt][0] = Wm[(kt * 8 + tig) * 64 + n];
                bfr[kt][nt][1] = Wm[(kt * 8 + tig + 4) * 64 + n];
            }

        float alv[2][2], arv[2][2];
#pragma unroll
        for (int nt = 0; nt < 2; nt++) {
            int c = m2 * 64 + nq * 16 + nt * 8 + 2 * tig;
            alv[nt][0] = al[c]; alv[nt][1] = al[c + 1];
            arv[nt][0] = ar[c]; arv[nt][1] = ar[c + 1];
        }

        __half* fbase = g_feat_h[slot];

#pragma unroll
        for (int mt = 0; mt < 4; mt++) {
            int rb = mq * 64 + mt * 16;
            float acc[2][4];
#pragma unroll
            for (int nt = 0; nt < 2; nt++)
#pragma unroll
                for (int i = 0; i < 4; i++) acc[nt][i] = 0.0f;

#pragma unroll
            for (int kt = 0; kt < 8; kt++) {
                int cb = kt * 8;
                unsigned int a0 = hsU[(rb + g) * HS_STRIDE + cb + tig];
                unsigned int a1 = hsU[(rb + g + 8) * HS_STRIDE + cb + tig];
                unsigned int a2 = hsU[(rb + g) * HS_STRIDE + cb + tig + 4];
                unsigned int a3 = hsU[(rb + g + 8) * HS_STRIDE + cb + tig + 4];
                mma_tf32(acc[0], a0, a1, a2, a3, bfr[kt][0][0], bfr[kt][0][1]);
                mma_tf32(acc[1], a0, a1, a2, a3, bfr[kt][1][0], bfr[kt][1][1]);
            }

            int r0 = row0 + rb + g, r1 = r0 + 8;
            float pel0 = 0.f, pel1 = 0.f, per0 = 0.f, per1 = 0.f;
#pragma unroll
            for (int nt = 0; nt < 2; nt++) {
                int c0 = nq * 16 + nt * 8 + 2 * tig;
                if (r0 < NN)
                    *(__half2*)&fbase[(size_t)r0 * 64 + c0] =
                        __floats2half2_rn(acc[nt][0], acc[nt][1]);
                if (r1 < NN)
                    *(__half2*)&fbase[(size_t)r1 * 64 + c0] =
                        __floats2half2_rn(acc[nt][2], acc[nt][3]);
                pel0 += acc[nt][0] * alv[nt][0] + acc[nt][1] * alv[nt][1];
                pel1 += acc[nt][2] * alv[nt][0] + acc[nt][3] * alv[nt][1];
                per0 += acc[nt][0] * arv[nt][0] + acc[nt][1] * arv[nt][1];
                per1 += acc[nt][2] * arv[nt][0] + acc[nt][3] * arv[nt][1];
            }
            pel0 += __shfl_xor_sync(~0u, pel0, 1); pel0 += __shfl_xor_sync(~0u, pel0, 2);
            pel1 += __shfl_xor_sync(~0u, pel1, 1); pel1 += __shfl_xor_sync(~0u, pel1, 2);
            per0 += __shfl_xor_sync(~0u, per0, 1); per0 += __shfl_xor_sync(~0u, per0, 2);
            per1 += __shfl_xor_sync(~0u, per1, 1); per1 += __shfl_xor_sync(~0u, per1, 2);
            if (tig == 0) {
                atomicAdd(&el_s[m2 * 128 + rb + g], pel0);
                atomicAdd(&el_s[m2 * 128 + rb + g + 8], pel1);
                atomicAdd(&er_s[m2 * 128 + rb + g], per0);
                atomicAdd(&er_s[m2 * 128 + rb + g + 8], per1);
            }
        }
    }

    __syncthreads();
    {
        int m2 = tid >> 7;            // 0/1
        int r  = tid & 127;
        int row = row0 + r;
        if (row < NN) {
            int slot = 2 * type + m2;
            g_el[slot][row] = el_s[m2 * 128 + r];
            g_er[slot][row] = er_s[m2 * 128 + r];
        }
    }
}

// ---------------- K2: single-pass scan (decoupled lookback) -----------------
__global__ void __launch_bounds__(256) k_scan()
{
    __shared__ int buf[256];
    __shared__ int base_sh;
    int slot = blockIdx.y;
    int bx = blockIdx.x;
    int tid = threadIdx.x;

    int i = bx * 256 + tid;
    int v = (i < NN) ? g_cnt[slot][i] : 0;
    buf[tid] = v;
    __syncthreads();
    for (int off = 1; off < 256; off <<= 1) {
        int x = (tid >= off) ? buf[tid - off] : 0;
        __syncthreads();
        buf[tid] += x;
        __syncthreads();
    }
    int agg = buf[255];

    if (tid == 0) {
        if (bx == 0) {
            atomicExch(&g_scan_st[slot][0],
                       (2ull << 62) | (unsigned long long)(unsigned int)agg);
            base_sh = 0;
        } else {
            atomicExch(&g_scan_st[slot][bx],
                       (1ull << 62) | (unsigned long long)(unsigned int)agg);
            long long prefix = 0;
            int j = bx - 1;
            while (j >= 0) {
                unsigned long long st = atomicAdd(&g_scan_st[slot][j], 0ull);
                unsigned long long flag = st >> 62;
                if (flag == 0) continue;                     // not ready, poll
                prefix += (long long)(unsigned int)(st & 0xFFFFFFFFull);
                if (flag == 2) break;
                j--;
            }
            atomicExch(&g_scan_st[slot][bx],
                       (2ull << 62) | (unsigned long long)(unsigned int)(prefix + agg));
            base_sh = (int)prefix;
        }
    }
    __syncthreads();

    if (i < NN) {
        g_rowptr[slot][i] = base_sh + buf[tid] - v;
        g_cnt[slot][i] = 0;      // restore invariant for next call
        g_cur[slot][i] = 0;      // scatter cursor
    }
    if (bx == NBLK - 1 && tid == 0) g_rowptr[slot][NN] = EE;
}

// ---------------- K3: scatter (src, exp(score)) into CSR --------------------
__global__ void k_scatter(
    const int* __restrict__ u_src, const int* __restrict__ u_dst,
    const int* __restrict__ i_src, const int* __restrict__ i_dst)
{
    int slot = 2 * blockIdx.z + blockIdx.y;
    if (blockIdx.x < NBLK && threadIdx.x == 0)
        g_scan_st[slot][blockIdx.x] = 0ull;
    const int* src = (blockIdx.z ? i_src : u_src) + (size_t)blockIdx.y * EE;
    const int* dst = (blockIdx.z ? i_dst : u_dst) + (size_t)blockIdx.y * EE;
    int i = blockIdx.x * 256 + threadIdx.x;
    if (i >= EE) return;
    int s = src[i], d = dst[i];
    float e = g_el[slot][s] + g_er[slot][d];
    e = (e >= 0.0f) ? e : 0.2f * e;          // leaky_relu 0.2
    float ex = __expf(e);
    int pos = g_rowptr[slot][d] + atomicAdd(&g_cur[slot][d], 1);
    g_csr[slot][pos] =
        ((unsigned long long)__float_as_uint(ex) << 32) | (unsigned int)s;
}

// ---------------- K4: aggregate, 16 lanes/node, dual edge streams -----------
// Lanes 0-7 of the 16-lane group take even CSR entries, lanes 8-15 odd;
// each stream pipelines 2 edges -> 4 gathers in flight per node.
__global__ void __launch_bounds__(256) k_aggr()
{
    int slot = blockIdx.y;
    int t = blockIdx.x * 256 + threadIdx.x;
    int node = t >> 4;
    int l16  = t & 15;
    int sub  = l16 & 7;          // column group: cols sub*8 .. sub*8+7
    int g2   = l16 >> 3;         // edge stream 0/1
    if (node >= NN) return;

    int start = g_rowptr[slot][node];
    int end   = g_rowptr[slot][node + 1];

    float acc[8] = {0.f, 0.f, 0.f, 0.f, 0.f, 0.f, 0.f, 0.f};
    float den = 0.0f;
    const __half* fb = g_feat_h[slot];
    const unsigned long long* csr = g_csr[slot];

    int p = start + g2;
    // pipelined: edges p and p+2 of this stream in flight together
    for (; p + 2 < end; p += 4) {
        unsigned long long pk0 = csr[p];
        unsigned long long pk1 = csr[p + 2];
        int s0 = (int)(unsigned int)pk0;
        int s1 = (int)(unsigned int)pk1;
        uint4 hva = *(const uint4*)&fb[(size_t)s0 * 64 + sub * 8];
        uint4 hvb = *(const uint4*)&fb[(size_t)s1 * 64 + sub * 8];
        float ex0 = __uint_as_float((unsigned int)(pk0 >> 32));
        float ex1 = __uint_as_float((unsigned int)(pk1 >> 32));
        den += ex0 + ex1;
        float2 a0 = __half22float2(*(__half2*)&hva.x);
        float2 a1 = __half22float2(*(__half2*)&hva.y);
        float2 a2 = __half22float2(*(__half2*)&hva.z);
        float2 a3 = __half22float2(*(__half2*)&hva.w);
        float2 b0 = __half22float2(*(__half2*)&hvb.x);
        float2 b1 = __half22float2(*(__half2*)&hvb.y);
        float2 b2 = __half22float2(*(__half2*)&hvb.z);
        float2 b3 = __half22float2(*(__half2*)&hvb.w);
        acc[0] += ex0 * a0.x + ex1 * b0.x;
        acc[1] += ex0 * a0.y + ex1 * b0.y;
        acc[2] += ex0 * a1.x + ex1 * b1.x;
        acc[3] += ex0 * a1.y + ex1 * b1.y;
        acc[4] += ex0 * a2.x + ex1 * b2.x;
        acc[5] += ex0 * a2.y + ex1 * b2.y;
        acc[6] += ex0 * a3.x + ex1 * b3.x;
        acc[7] += ex0 * a3.y + ex1 * b3.y;
    }
    // stream tail (0 or 1 edge left for this stream)
    if (p < end) {
        unsigned long long pk = csr[p];
        int s = (int)(unsigned int)pk;
        float ex = __uint_as_float((unsigned int)(pk >> 32));
        den += ex;
        uint4 hv = *(const uint4*)&fb[(size_t)s * 64 + sub * 8];
        float2 f0 = __half22float2(*(__half2*)&hv.x);
        float2 f1 = __half22float2(*(__half2*)&hv.y);
        float2 f2 = __half22float2(*(__half2*)&hv.z);
        float2 f3 = __half22float2(*(__half2*)&hv.w);
        acc[0] += ex * f0.x; acc[1] += ex * f0.y;
        acc[2] += ex * f1.x; acc[3] += ex * f1.y;
        acc[4] += ex * f2.x; acc[5] += ex * f2.y;
        acc[6] += ex * f3.x; acc[7] += ex * f3.y;
    }

    // combine the two streams (lanes l and l^8 belong to the same node)
#pragma unroll
    for (int j = 0; j < 8; j++)
        acc[j] += __shfl_xor_sync(0xffffffffu, acc[j], 8);
    den += __shfl_xor_sync(0xffffffffu, den, 8);

    if (g2 == 0) {
        float inv = __fdividef(1.0f, den + 1e-9f);
        __half2 h0 = __floats2half2_rn(acc[0] * inv, acc[1] * inv);
        __half2 h1 = __floats2half2_rn(acc[2] * inv, acc[3] * inv);
        __half2 h2 = __floats2half2_rn(acc[4] * inv, acc[5] * inv);
        __half2 h3 = __floats2half2_rn(acc[6] * inv, acc[7] * inv);
        uint4 pk = make_uint4(*(unsigned int*)&h0, *(unsigned int*)&h1,
                              *(unsigned int*)&h2, *(unsigned int*)&h3);
        *(uint4*)&g_z_h[slot][(size_t)node * 64 + sub * 8] = pk;
    }
}

// ---------------- K5: semantic logits via mma.sync bf16 ---------------------
#define SEM_TILE_STRIDE 72

__global__ void __launch_bounds__(256) k_sem_mma(
    const float* __restrict__ uW1, const float* __restrict__ ub1,
    const float* __restrict__ uW2, const float* __restrict__ ugb,
    const float* __restrict__ iW1, const float* __restrict__ ib1,
    const float* __restrict__ iW2, const float* __restrict__ igb)
{
    __shared__ __align__(16) __nv_bfloat16 tile[2][32][SEM_TILE_STRIDE];
    __shared__ float gbs[128];
    __shared__ float wsum[8];

    int t = blockIdx.y;
    const float* W1 = t ? iW1 : uW1;
    const float* b1 = t ? ib1 : ub1;
    const float* W2 = t ? iW2 : uW2;
    const float* gb = t ? igb : ugb;

    int tid  = threadIdx.x;
    int warp = tid >> 5;
    int lane = tid & 31;
    int slot = warp >> 2;
    int nq   = warp & 3;

    if (tid < 128) gbs[tid] = gb[tid];

    unsigned int bfr[4][4][2];
    {
        int n = nq * 32 + (lane >> 2);
        int k0 = (lane & 3) * 2;
#pragma unroll
        for (int kt = 0; kt < 4; kt++) {
            int k = kt * 16 + k0;
#pragma unroll
            for (int nt = 0; nt < 4; nt++) {
                int nn = n + nt * 8;
                bfr[kt][nt][0] = bf2(W1[(size_t)k * 128 + nn],
                                     W1[(size_t)(k + 1) * 128 + nn]);
                bfr[kt][nt][1] = bf2(W1[(size_t)(k + 8) * 128 + nn],
                                     W1[(size_t)(k + 9) * 128 + nn]);
            }
        }
    }
    float w2v[4][2], bsv[4][2];
#pragma unroll
    for (int nt = 0; nt < 4; nt++) {
        int c = nq * 32 + nt * 8 + (lane & 3) * 2;
        w2v[nt][0] = W2[c];     w2v[nt][1] = W2[c + 1];
        bsv[nt][0] = b1[c];     bsv[nt][1] = b1[c + 1];
    }

    int s_slot = tid >> 7;
    int tid2   = tid & 127;
    int s_row  = tid2 >> 2;
    int s_colq = (tid2 & 3) * 16;

    int ld_row = lane & 15;
    int ld_off = (lane >> 4) * 16;

    float s = 0.0f;

    const int NITER = NN / 32;
    __syncthreads();
    for (int it = blockIdx.x; it < NITER; it += gridDim.x) {
        int row = it * 32 + s_row;
        const __half* zrow = g_z_h[2 * t + s_slot] + (size_t)row * 64 + s_colq;
        uint4 va = *(const uint4*)zrow;
        uint4 vb = *(const uint4*)(zrow + 8);
        unsigned int wv[8] = {va.x, va.y, va.z, va.w, vb.x, vb.y, vb.z, vb.w};
        unsigned int* drow = (unsigned int*)&tile[s_slot][s_row][0];
#pragma unroll
        for (int j = 0; j < 8; j++) {
            float2 f = __half22float2(*(__half2*)&wv[j]);
            int c = s_colq + 2 * j;
            drow[(s_colq >> 1) + j] =
                bf2(elu_fast(f.x + gbs[s_slot * 64 + c]),
                    elu_fast(f.y + gbs[s_slot * 64 + c + 1]));
        }
        __syncthreads();

#pragma unroll
        for (int mt = 0; mt < 2; mt++) {
            unsigned int a[4][4];
            const __nv_bfloat16* ap = &tile[slot][mt * 16 + ld_row][0];
            unsigned int abase = (unsigned int)__cvta_generic_to_shared(ap) + ld_off;
#pragma unroll
            for (int kt = 0; kt < 4; kt++) {
                asm volatile(
                    "ldmatrix.sync.aligned.m8n8.x4.shared.b16 {%0,%1,%2,%3}, [%4];"
                    : "=r"(a[kt][0]), "=r"(a[kt][1]), "=r"(a[kt][2]), "=r"(a[kt][3])
                    : "r"(abase + kt * 32));
            }
#pragma unroll
            for (int nt = 0; nt < 4; nt++) {
                float c0 = 0.f, c1 = 0.f, c2 = 0.f, c3 = 0.f;
#pragma unroll
                for (int kt = 0; kt < 4; kt++)
                    mma_bf16(c0, c1, c2, c3,
                             a[kt][0], a[kt][1], a[kt][2], a[kt][3],
                             bfr[kt][nt][0], bfr[kt][nt][1]);
                s += tanh_fast(c0 + bsv[nt][0]) * w2v[nt][0];
                s += tanh_fast(c1 + bsv[nt][1]) * w2v[nt][1];
                s += tanh_fast(c2 + bsv[nt][0]) * w2v[nt][0];
                s += tanh_fast(c3 + bsv[nt][1]) * w2v[nt][1];
            }
        }
        __syncthreads();
    }

#pragma unroll
    for (int off = 16; off > 0; off >>= 1)
        s += __shfl_xor_sync(0xffffffffu, s, off);
    if (lane == 0) wsum[warp] = s;
    __syncthreads();
    if (tid < 2) {
        float tot = wsum[tid * 4] + wsum[tid * 4 + 1]
                  + wsum[tid * 4 + 2] + wsum[tid * 4 + 3];
        atomicAdd(&g_w[2 * t + tid], tot);
    }
}

// ---------------- K6: gather + bias/ELU + beta + GEMM + ReLU + LN ------------
__global__ void __launch_bounds__(256) k_final(
    const int* __restrict__ user_idx, const int* __restrict__ item_idx,
    const int* __restrict__ neg_idx,
    const float* __restrict__ u_gb, const float* __restrict__ i_gb,
    const float* __restrict__ userW, const float* __restrict__ userb,
    const float* __restrict__ itemW, const float* __restrict__ itemb,
    const float* __restrict__ ln_g, const float* __restrict__ ln_b,
    float* __restrict__ out)
{
    __shared__ float Ws[4096];
    __shared__ float bs[64], gs[64], lbs[64];
    __shared__ float gb0[64], gb1[64];
    __shared__ float embs[4][64];
    __shared__ float red[4][2];

    int tid = threadIdx.x;
    int tx = tid & 63, ty = tid >> 6;
    int r0 = blockIdx.x * 4;
    bool isUser = (r0 < BB);
    const float* W    = isUser ? userW : itemW;
    const float* bias = isUser ? userb : itemb;
    const float* gbm  = isUser ? u_gb : i_gb;

    for (int i = tid; i < 4096; i += 256) Ws[i] = W[i];
    if (tid < 64) {
        bs[tid] = bias[tid]; gs[tid] = ln_g[tid]; lbs[tid] = ln_b[tid];
        gb0[tid] = gbm[tid]; gb1[tid] = gbm[64 + tid];
    }

    int r = r0 + ty;
    int type, idx;
    if (r < BB)            { type = 0; idx = user_idx[r]; }
    else if (r < 2 * BB)   { type = 1; idx = item_idx[r - BB]; }
    else                   { type = 1; idx = neg_idx[r - 2 * BB]; }

    float w0 = g_w[2 * type] * (1.0f / NN);
    float w1 = g_w[2 * type + 1] * (1.0f / NN);
    float mx = fmaxf(w0, w1);
    float e0 = __expf(w0 - mx), e1 = __expf(w1 - mx);
    float binv = 1.0f / (e0 + e1);
    float b0 = e0 * binv, b1 = e1 * binv;

    __syncthreads();
    float zr0 = __half2float(g_z_h[2 * type][(size_t)idx * 64 + tx]) + gb0[tx];
    float zr1 = __half2float(g_z_h[2 * type + 1][(size_t)idx * 64 + tx]) + gb1[tx];
    float emb = b0 * elu_fast(zr0) + b1 * elu_fast(zr1);
    embs[ty][tx] = emb;
    __syncthreads();

    float y = bs[tx];
#pragma unroll 16
    for (int k = 0; k < 64; k++) y += embs[ty][k] * Ws[k * 64 + tx];
    y = fmaxf(y, 0.0f);

    float s = y;
#pragma unroll
    for (int off = 16; off > 0; off >>= 1) s += __shfl_xor_sync(0xffffffffu, s, off);
    int half = tx >> 5;
    if ((tx & 31) == 0) red[ty][half] = s;
    __syncthreads();
    float mu = (red[ty][0] + red[ty][1]) * (1.0f / 64.0f);
    float dv = y - mu;
    float s2 = dv * dv;
#pragma unroll
    for (int off = 16; off > 0; off >>= 1) s2 += __shfl_xor_sync(0xffffffffu, s2, off);
    __syncthreads();
    if ((tx & 31) == 0) red[ty][half] = s2;
    __syncthreads();
    float var = (red[ty][0] + red[ty][1]) * (1.0f / 64.0f);
    float o = gs[tx] * dv * rsqrtf(var + 1e-5f) + lbs[tx];
    out[(size_t)r * 64 + tx] = o;
}

// ---------------- host ------------------------------------------------------
extern "C" void kernel_launch(void* const* d_in, const int* in_sizes, int n_in,
                              void* d_out, int out_size)
{
    const int*   user_idx  = (const int*)d_in[0];
    const int*   item_idx  = (const int*)d_in[1];
    const int*   neg_idx   = (const int*)d_in[2];
    const float* user_feat = (const float*)d_in[3];
    const float* item_feat = (const float*)d_in[4];
    const int*   u_src = (const int*)d_in[5];
    const int*   u_dst = (const int*)d_in[6];
    const int*   i_src = (const int*)d_in[7];
    const int*   i_dst = (const int*)d_in[8];
    const float* u_W  = (const float*)d_in[9];
    const float* u_al = (const float*)d_in[10];
    const float* u_ar = (const float*)d_in[11];
    const float* u_b  = (const float*)d_in[12];
    const float* i_W  = (const float*)d_in[13];
    const float* i_al = (const float*)d_in[14];
    const float* i_ar = (const float*)d_in[15];
    const float* i_b  = (const float*)d_in[16];
    const float* u_saW1 = (const float*)d_in[17];
    const float* u_sab1 = (const float*)d_in[18];
    const float* u_saW2 = (const float*)d_in[19];
    const float* i_saW1 = (const float*)d_in[20];
    const float* i_sab1 = (const float*)d_in[21];
    const float* i_saW2 = (const float*)d_in[22];
    const float* userW = (const float*)d_in[23];
    const float* userb = (const float*)d_in[24];
    const float* itemW = (const float*)d_in[25];
    const float* itemb = (const float*)d_in[26];
    const float* ln_g  = (const float*)d_in[27];
    const float* ln_b  = (const float*)d_in[28];
    float* out = (float*)d_out;

    cudaFuncSetAttribute(k_fused1,
                         cudaFuncAttributeMaxDynamicSharedMemorySize, K1F_SMEM);

    dim3 gridF(NGB + 2 * NHB, 2);                // 2736 x type
    dim3 gridS(NBLK, 4);                         // 391 x slot
    dim3 gridE((EE + 255) / 256, 2, 2);          // 1954 x m x type
    dim3 gridG((NN * 16 + 255) / 256, 4);        // 6250 x slot

    k_fused1<<<gridF, 256, K1F_SMEM>>>(user_feat, item_feat, u_W, i_W,
                                       u_al, i_al, u_ar, i_ar, u_dst, i_dst);
    k_scan<<<gridS, 256>>>();
    k_scatter<<<gridE, 256>>>(u_src, u_dst, i_src, i_dst);
    k_aggr<<<gridG, 256>>>();

    dim3 semGrid(256, 2);
    k_sem_mma<<<semGrid, 256>>>(u_saW1, u_sab1, u_saW2, u_b,
                                i_saW1, i_sab1, i_saW2, i_b);
    k_final<<<(3 * BB) / 4, 256>>>(user_idx, item_idx, neg_idx, u_b, i_b,
                                   userW, userb, itemW, itemb, ln_g, ln_b, out);
}

// round 14
// speedup vs baseline: 1.0807x; 1.0807x over previous
#include <cuda_runtime.h>
#include <cuda_bf16.h>
#include <cuda_fp16.h>
#include <math.h>

#define NN 100000
#define EE 500000
#define BB 8192
#define NBLK 391                     // ceil(NN/256)
#define NGB 782                      // gemm blocks per type (ceil(NN/128))
#define NHB 977                      // hist blocks per metapath (512 edges each)

// ---------------- scratch (device globals) ----------------------------------
__device__ __half g_feat_h[4][NN * 64];        // fp16 feat per slot
__device__ __half g_z_h[4][NN * 64];           // fp16 normalized GAT output
__device__ float g_el[4][NN];
__device__ int   g_cnt[4][NN];                 // histogram (zero at call entry)
// per-dst packed info: x=rowptr, y=cursor, z=er bits, w=unused
__device__ __align__(16) int4 g_dinfo[4][NN + 1];
__device__ unsigned long long g_scan_st[4][NBLK];  // lookback state (zeroed by scatter)
__device__ __align__(16) unsigned long long g_csr[4][EE];  // (exp << 32) | src
__device__ float g_w[4];

// ---------------- helpers ----------------------------------------------------
__device__ __forceinline__ float tanh_fast(float x) {
    float y; asm("tanh.approx.f32 %0, %1;" : "=f"(y) : "f"(x)); return y;
}
__device__ __forceinline__ float elu_fast(float x) {
    return x > 0.f ? x : (__expf(x) - 1.f);
}
__device__ __forceinline__ unsigned int bf2(float lo, float hi) {
    __nv_bfloat162 v = __floats2bfloat162_rn(lo, hi);
    return *reinterpret_cast<unsigned int*>(&v);
}
__device__ __forceinline__ unsigned int to_tf32(float f) {
    unsigned int u; asm("cvt.rna.tf32.f32 %0, %1;" : "=r"(u) : "f"(f)); return u;
}
__device__ __forceinline__ void mma_bf16(
    float& c0, float& c1, float& c2, float& c3,
    unsigned int a0, unsigned int a1, unsigned int a2, unsigned int a3,
    unsigned int b0, unsigned int b1)
{
    asm("mma.sync.aligned.m16n8k16.row.col.f32.bf16.bf16.f32 "
        "{%0,%1,%2,%3}, {%4,%5,%6,%7}, {%8,%9}, {%0,%1,%2,%3};"
        : "+f"(c0), "+f"(c1), "+f"(c2), "+f"(c3)
        : "r"(a0), "r"(a1), "r"(a2), "r"(a3), "r"(b0), "r"(b1));
}
__device__ __forceinline__ void mma_tf32(
    float* c, unsigned int a0, unsigned int a1, unsigned int a2, unsigned int a3,
    unsigned int b0, unsigned int b1)
{
    asm("mma.sync.aligned.m16n8k8.row.col.f32.tf32.tf32.f32 "
        "{%0,%1,%2,%3}, {%4,%5,%6,%7}, {%8,%9}, {%0,%1,%2,%3};"
        : "+f"(c[0]), "+f"(c[1]), "+f"(c[2]), "+f"(c[3])
        : "r"(a0), "r"(a1), "r"(a2), "r"(a3), "r"(b0), "r"(b1));
}

// ---------------- K1: fused feat GEMM (both metapaths) + degree histogram ---
// W fragments loaded straight from L2-hot global (no smem staging) -> 36KB smem.
#define HS_STRIDE 68
#define K1F_SMEM ((128 * HS_STRIDE + 512) * 4)

__global__ void __launch_bounds__(256) k_fused1(
    const float* __restrict__ h_u, const float* __restrict__ h_i,
    const float* __restrict__ W_u, const float* __restrict__ W_i,
    const float* __restrict__ al_u, const float* __restrict__ al_i,
    const float* __restrict__ ar_u, const float* __restrict__ ar_i,
    const int* __restrict__ u_dst, const int* __restrict__ i_dst)
{
    int type = blockIdx.y;
    int tid  = threadIdx.x;

    // ---- histogram role ----
    if (blockIdx.x >= NGB) {
        int hb = blockIdx.x - NGB;           // 0 .. 2*NHB-1
        int m  = hb >= NHB;
        int b  = hb - m * NHB;
        int slot = 2 * type + m;
        const int* dst = (type ? i_dst : u_dst) + (size_t)m * EE;
        int e0 = b * 512 + tid;
        if (e0 < EE) atomicAdd(&g_cnt[slot][dst[e0]], 1);
        int e1 = e0 + 256;
        if (e1 < EE) atomicAdd(&g_cnt[slot][dst[e1]], 1);
        return;
    }

    // ---- gemm role ----
    extern __shared__ unsigned int smemu[];
    unsigned int* hsU = smemu;                  // 128 x 68 (tf32 bits)
    float* el_s = (float*)(hsU + 128 * HS_STRIDE);  // 2 x 128
    float* er_s = el_s + 256;                   // 2 x 128

    const float* h  = type ? h_i : h_u;
    const float* W  = type ? W_i : W_u;
    const float* al = type ? al_i : al_u;
    const float* ar = type ? ar_i : ar_u;

    int row0 = blockIdx.x * 128;

    if (blockIdx.x == 0 && type == 0 && tid < 4) g_w[tid] = 0.0f;

    {
        int r  = tid >> 1;
        int kq = (tid & 1) * 32;
        int grow = row0 + r;
        unsigned int* dst = &hsU[r * HS_STRIDE + kq];
        if (grow < NN) {
            const float4* hp = (const float4*)&h[(size_t)grow * 64 + kq];
#pragma unroll
            for (int j = 0; j < 8; j++) {
                float4 v = hp[j];
                dst[4 * j + 0] = to_tf32(v.x);
                dst[4 * j + 1] = to_tf32(v.y);
                dst[4 * j + 2] = to_tf32(v.z);
                dst[4 * j + 3] = to_tf32(v.w);
            }
        } else {
#pragma unroll
            for (int j = 0; j < 32; j++) dst[j] = 0u;
        }
    }
    el_s[tid] = 0.0f;
    er_s[tid] = 0.0f;
    __syncthreads();

    int lane = tid & 31, warp = tid >> 5;
    int g = lane >> 2, tig = lane & 3;
    int mq = warp & 1, nq = warp >> 1;

#pragma unroll
    for (int m2 = 0; m2 < 2; m2++) {
        int slot = 2 * type + m2;
        const float* Wm = W + m2 * 4096;

        unsigned int bfr[8][2][2];
#pragma unroll
        for (int kt = 0; kt < 8; kt++)
#pragma unroll
            for (int nt = 0; nt < 2; nt++) {
                int n = nq * 16 + nt * 8 + g;
                bfr[kt][nt][0] = to_tf32(Wm[(kt * 8 + tig) * 64 + n]);
                bfr[kt][nt][1] = to_tf32(Wm[(kt * 8 + tig + 4) * 64 + n]);
            }

        float alv[2][2], arv[2][2];
#pragma unroll
        for (int nt = 0; nt < 2; nt++) {
            int c = m2 * 64 + nq * 16 + nt * 8 + 2 * tig;
            alv[nt][0] = al[c]; alv[nt][1] = al[c + 1];
            arv[nt][0] = ar[c]; arv[nt][1] = ar[c + 1];
        }

        __half* fbase = g_feat_h[slot];

#pragma unroll
        for (int mt = 0; mt < 4; mt++) {
            int rb = mq * 64 + mt * 16;
            float acc[2][4];
#pragma unroll
            for (int nt = 0; nt < 2; nt++)
#pragma unroll
                for (int i = 0; i < 4; i++) acc[nt][i] = 0.0f;

#pragma unroll
            for (int kt = 0; kt < 8; kt++) {
                int cb = kt * 8;
                unsigned int a0 = hsU[(rb + g) * HS_STRIDE + cb + tig];
                unsigned int a1 = hsU[(rb + g + 8) * HS_STRIDE + cb + tig];
                unsigned int a2 = hsU[(rb + g) * HS_STRIDE + cb + tig + 4];
                unsigned int a3 = hsU[(rb + g + 8) * HS_STRIDE + cb + tig + 4];
                mma_tf32(acc[0], a0, a1, a2, a3, bfr[kt][0][0], bfr[kt][0][1]);
                mma_tf32(acc[1], a0, a1, a2, a3, bfr[kt][1][0], bfr[kt][1][1]);
            }

            int r0 = row0 + rb + g, r1 = r0 + 8;
            float pel0 = 0.f, pel1 = 0.f, per0 = 0.f, per1 = 0.f;
#pragma unroll
            for (int nt = 0; nt < 2; nt++) {
                int c0 = nq * 16 + nt * 8 + 2 * tig;
                if (r0 < NN)
                    *(__half2*)&fbase[(size_t)r0 * 64 + c0] =
                        __floats2half2_rn(acc[nt][0], acc[nt][1]);
                if (r1 < NN)
                    *(__half2*)&fbase[(size_t)r1 * 64 + c0] =
                        __floats2half2_rn(acc[nt][2], acc[nt][3]);
                pel0 += acc[nt][0] * alv[nt][0] + acc[nt][1] * alv[nt][1];
                pel1 += acc[nt][2] * alv[nt][0] + acc[nt][3] * alv[nt][1];
                per0 += acc[nt][0] * arv[nt][0] + acc[nt][1] * arv[nt][1];
                per1 += acc[nt][2] * arv[nt][0] + acc[nt][3] * arv[nt][1];
            }
            pel0 += __shfl_xor_sync(~0u, pel0, 1); pel0 += __shfl_xor_sync(~0u, pel0, 2);
            pel1 += __shfl_xor_sync(~0u, pel1, 1); pel1 += __shfl_xor_sync(~0u, pel1, 2);
            per0 += __shfl_xor_sync(~0u, per0, 1); per0 += __shfl_xor_sync(~0u, per0, 2);
            per1 += __shfl_xor_sync(~0u, per1, 1); per1 += __shfl_xor_sync(~0u, per1, 2);
            if (tig == 0) {
                atomicAdd(&el_s[m2 * 128 + rb + g], pel0);
                atomicAdd(&el_s[m2 * 128 + rb + g + 8], pel1);
                atomicAdd(&er_s[m2 * 128 + rb + g], per0);
                atomicAdd(&er_s[m2 * 128 + rb + g + 8], per1);
            }
        }
    }

    __syncthreads();
    {
        int m2 = tid >> 7;            // 0/1
        int r  = tid & 127;
        int row = row0 + r;
        if (row < NN) {
            int slot = 2 * type + m2;
            g_el[slot][row] = el_s[m2 * 128 + r];
            g_dinfo[slot][row].z = __float_as_int(er_s[m2 * 128 + r]);
        }
    }
}

// ---------------- K2: single-pass scan (decoupled lookback) -----------------
// Writes dinfo.x = rowptr, dinfo.y = 0 (cursor); zeroes cnt.
__global__ void __launch_bounds__(256) k_scan()
{
    __shared__ int buf[256];
    __shared__ int base_sh;
    int slot = blockIdx.y;
    int bx = blockIdx.x;
    int tid = threadIdx.x;

    int i = bx * 256 + tid;
    int v = (i < NN) ? g_cnt[slot][i] : 0;
    buf[tid] = v;
    __syncthreads();
    for (int off = 1; off < 256; off <<= 1) {
        int x = (tid >= off) ? buf[tid - off] : 0;
        __syncthreads();
        buf[tid] += x;
        __syncthreads();
    }
    int agg = buf[255];

    if (tid == 0) {
        if (bx == 0) {
            atomicExch(&g_scan_st[slot][0],
                       (2ull << 62) | (unsigned long long)(unsigned int)agg);
            base_sh = 0;
        } else {
            atomicExch(&g_scan_st[slot][bx],
                       (1ull << 62) | (unsigned long long)(unsigned int)agg);
            long long prefix = 0;
            int j = bx - 1;
            while (j >= 0) {
                unsigned long long st = atomicAdd(&g_scan_st[slot][j], 0ull);
                unsigned long long flag = st >> 62;
                if (flag == 0) continue;                     // not ready, poll
                prefix += (long long)(unsigned int)(st & 0xFFFFFFFFull);
                if (flag == 2) break;
                j--;
            }
            atomicExch(&g_scan_st[slot][bx],
                       (2ull << 62) | (unsigned long long)(unsigned int)(prefix + agg));
            base_sh = (int)prefix;
        }
    }
    __syncthreads();

    if (i < NN) {
        g_dinfo[slot][i].x = base_sh + buf[tid] - v;
        g_dinfo[slot][i].y = 0;
        g_cnt[slot][i] = 0;      // restore invariant for next call
    }
    if (bx == NBLK - 1 && tid == 0) g_dinfo[slot][NN].x = EE;
}

// ---------------- K3: scatter (src, exp(score)) into CSR --------------------
__global__ void k_scatter(
    const int* __restrict__ u_src, const int* __restrict__ u_dst,
    const int* __restrict__ i_src, const int* __restrict__ i_dst)
{
    int slot = 2 * blockIdx.z + blockIdx.y;
    if (blockIdx.x < NBLK && threadIdx.x == 0)
        g_scan_st[slot][blockIdx.x] = 0ull;
    const int* src = (blockIdx.z ? i_src : u_src) + (size_t)blockIdx.y * EE;
    const int* dst = (blockIdx.z ? i_dst : u_dst) + (size_t)blockIdx.y * EE;
    int i = blockIdx.x * 256 + threadIdx.x;
    if (i >= EE) return;
    int s = src[i], d = dst[i];
    int4 di = g_dinfo[slot][d];                     // rowptr + er in one 16B load
    float e = g_el[slot][s] + __int_as_float(di.z);
    e = (e >= 0.0f) ? e : 0.2f * e;          // leaky_relu 0.2
    float ex = __expf(e);
    int pos = di.x + atomicAdd(&((int*)&g_dinfo[slot][d])[1], 1);
    g_csr[slot][pos] =
        ((unsigned long long)__float_as_uint(ex) << 32) | (unsigned int)s;
}

// ---------------- K4: node-parallel aggregate (pipelined pairs, R12) --------
__global__ void __launch_bounds__(256) k_aggr()
{
    int slot = blockIdx.y;
    int t = blockIdx.x * 256 + threadIdx.x;
    int node = t >> 3;
    int lane = t & 7;
    if (node >= NN) return;

    int start = g_dinfo[slot][node].x;
    int end   = g_dinfo[slot][node + 1].x;

    float acc[8] = {0.f, 0.f, 0.f, 0.f, 0.f, 0.f, 0.f, 0.f};
    float den = 0.0f;
    const __half* fb = g_feat_h[slot];
    const unsigned long long* csr = g_csr[slot];

    int p = start;
    if (p < end && (p & 1)) {
        unsigned long long pk = csr[p];
        int s = (int)(unsigned int)pk;
        float ex = __uint_as_float((unsigned int)(pk >> 32));
        den += ex;
        uint4 hv = *(const uint4*)&fb[(size_t)s * 64 + lane * 8];
        float2 f0 = __half22float2(*(__half2*)&hv.x);
        float2 f1 = __half22float2(*(__half2*)&hv.y);
        float2 f2 = __half22float2(*(__half2*)&hv.z);
        float2 f3 = __half22float2(*(__half2*)&hv.w);
        acc[0] += ex * f0.x; acc[1] += ex * f0.y;
        acc[2] += ex * f1.x; acc[3] += ex * f1.y;
        acc[4] += ex * f2.x; acc[5] += ex * f2.y;
        acc[6] += ex * f3.x; acc[7] += ex * f3.y;
        p++;
    }
    for (; p + 2 <= end; p += 2) {
        ulonglong2 pk2 = *(const ulonglong2*)&csr[p];
        int s0 = (int)(unsigned int)pk2.x;
        int s1 = (int)(unsigned int)pk2.y;
        float ex0 = __uint_as_float((unsigned int)(pk2.x >> 32));
        float ex1 = __uint_as_float((unsigned int)(pk2.y >> 32));
        uint4 hva = *(const uint4*)&fb[(size_t)s0 * 64 + lane * 8];
        uint4 hvb = *(const uint4*)&fb[(size_t)s1 * 64 + lane * 8];
        den += ex0 + ex1;
        float2 a0 = __half22float2(*(__half2*)&hva.x);
        float2 a1 = __half22float2(*(__half2*)&hva.y);
        float2 a2 = __half22float2(*(__half2*)&hva.z);
        float2 a3 = __half22float2(*(__half2*)&hva.w);
        float2 b0 = __half22float2(*(__half2*)&hvb.x);
        float2 b1 = __half22float2(*(__half2*)&hvb.y);
        float2 b2 = __half22float2(*(__half2*)&hvb.z);
        float2 b3 = __half22float2(*(__half2*)&hvb.w);
        acc[0] += ex0 * a0.x + ex1 * b0.x;
        acc[1] += ex0 * a0.y + ex1 * b0.y;
        acc[2] += ex0 * a1.x + ex1 * b1.x;
        acc[3] += ex0 * a1.y + ex1 * b1.y;
        acc[4] += ex0 * a2.x + ex1 * b2.x;
        acc[5] += ex0 * a2.y + ex1 * b2.y;
        acc[6] += ex0 * a3.x + ex1 * b3.x;
        acc[7] += ex0 * a3.y + ex1 * b3.y;
    }
    if (p < end) {
        unsigned long long pk = csr[p];
        int s = (int)(unsigned int)pk;
        float ex = __uint_as_float((unsigned int)(pk >> 32));
        den += ex;
        uint4 hv = *(const uint4*)&fb[(size_t)s * 64 + lane * 8];
        float2 f0 = __half22float2(*(__half2*)&hv.x);
        float2 f1 = __half22float2(*(__half2*)&hv.y);
        float2 f2 = __half22float2(*(__half2*)&hv.z);
        float2 f3 = __half22float2(*(__half2*)&hv.w);
        acc[0] += ex * f0.x; acc[1] += ex * f0.y;
        acc[2] += ex * f1.x; acc[3] += ex * f1.y;
        acc[4] += ex * f2.x; acc[5] += ex * f2.y;
        acc[6] += ex * f3.x; acc[7] += ex * f3.y;
    }

    float inv = __fdividef(1.0f, den + 1e-9f);
    __half2 h0 = __floats2half2_rn(acc[0] * inv, acc[1] * inv);
    __half2 h1 = __floats2half2_rn(acc[2] * inv, acc[3] * inv);
    __half2 h2 = __floats2half2_rn(acc[4] * inv, acc[5] * inv);
    __half2 h3 = __floats2half2_rn(acc[6] * inv, acc[7] * inv);
    uint4 pk = make_uint4(*(unsigned int*)&h0, *(unsigned int*)&h1,
                          *(unsigned int*)&h2, *(unsigned int*)&h3);
    *(uint4*)&g_z_h[slot][(size_t)node * 64 + lane * 8] = pk;
}

// ---------------- K5: semantic logits via mma.sync bf16 ---------------------
#define SEM_TILE_STRIDE 72

__global__ void __launch_bounds__(256) k_sem_mma(
    const float* __restrict__ uW1, const float* __restrict__ ub1,
    const float* __restrict__ uW2, const float* __restrict__ ugb,
    const float* __restrict__ iW1, const float* __restrict__ ib1,
    const float* __restrict__ iW2, const float* __restrict__ igb)
{
    __shared__ __align__(16) __nv_bfloat16 tile[2][32][SEM_TILE_STRIDE];
    __shared__ float gbs[128];
    __shared__ float wsum[8];

    int t = blockIdx.y;
    const float* W1 = t ? iW1 : uW1;
    const float* b1 = t ? ib1 : ub1;
    const float* W2 = t ? iW2 : uW2;
    const float* gb = t ? igb : ugb;

    int tid  = threadIdx.x;
    int warp = tid >> 5;
    int lane = tid & 31;
    int slot = warp >> 2;
    int nq   = warp & 3;

    if (tid < 128) gbs[tid] = gb[tid];

    unsigned int bfr[4][4][2];
    {
        int n = nq * 32 + (lane >> 2);
        int k0 = (lane & 3) * 2;
#pragma unroll
        for (int kt = 0; kt < 4; kt++) {
            int k = kt * 16 + k0;
#pragma unroll
            for (int nt = 0; nt < 4; nt++) {
                int nn = n + nt * 8;
                bfr[kt][nt][0] = bf2(W1[(size_t)k * 128 + nn],
                                     W1[(size_t)(k + 1) * 128 + nn]);
                bfr[kt][nt][1] = bf2(W1[(size_t)(k + 8) * 128 + nn],
                                     W1[(size_t)(k + 9) * 128 + nn]);
            }
        }
    }
    float w2v[4][2], bsv[4][2];
#pragma unroll
    for (int nt = 0; nt < 4; nt++) {
        int c = nq * 32 + nt * 8 + (lane & 3) * 2;
        w2v[nt][0] = W2[c];     w2v[nt][1] = W2[c + 1];
        bsv[nt][0] = b1[c];     bsv[nt][1] = b1[c + 1];
    }

    int s_slot = tid >> 7;
    int tid2   = tid & 127;
    int s_row  = tid2 >> 2;
    int s_colq = (tid2 & 3) * 16;

    int ld_row = lane & 15;
    int ld_off = (lane >> 4) * 16;

    float s = 0.0f;

    const int NITER = NN / 32;
    __syncthreads();
    for (int it = blockIdx.x; it < NITER; it += gridDim.x) {
        int row = it * 32 + s_row;
        const __half* zrow = g_z_h[2 * t + s_slot] + (size_t)row * 64 + s_colq;
        uint4 va = *(const uint4*)zrow;
        uint4 vb = *(const uint4*)(zrow + 8);
        unsigned int wv[8] = {va.x, va.y, va.z, va.w, vb.x, vb.y, vb.z, vb.w};
        unsigned int* drow = (unsigned int*)&tile[s_slot][s_row][0];
#pragma unroll
        for (int j = 0; j < 8; j++) {
            float2 f = __half22float2(*(__half2*)&wv[j]);
            int c = s_colq + 2 * j;
            drow[(s_colq >> 1) + j] =
                bf2(elu_fast(f.x + gbs[s_slot * 64 + c]),
                    elu_fast(f.y + gbs[s_slot * 64 + c + 1]));
        }
        __syncthreads();

#pragma unroll
        for (int mt = 0; mt < 2; mt++) {
            unsigned int a[4][4];
            const __nv_bfloat16* ap = &tile[slot][mt * 16 + ld_row][0];
            unsigned int abase = (unsigned int)__cvta_generic_to_shared(ap) + ld_off;
#pragma unroll
            for (int kt = 0; kt < 4; kt++) {
                asm volatile(
                    "ldmatrix.sync.aligned.m8n8.x4.shared.b16 {%0,%1,%2,%3}, [%4];"
                    : "=r"(a[kt][0]), "=r"(a[kt][1]), "=r"(a[kt][2]), "=r"(a[kt][3])
                    : "r"(abase + kt * 32));
            }
#pragma unroll
            for (int nt = 0; nt < 4; nt++) {
                float c0 = 0.f, c1 = 0.f, c2 = 0.f, c3 = 0.f;
#pragma unroll
                for (int kt = 0; kt < 4; kt++)
                    mma_bf16(c0, c1, c2, c3,
                             a[kt][0], a[kt][1], a[kt][2], a[kt][3],
                             bfr[kt][nt][0], bfr[kt][nt][1]);
                s += tanh_fast(c0 + bsv[nt][0]) * w2v[nt][0];
                s += tanh_fast(c1 + bsv[nt][1]) * w2v[nt][1];
                s += tanh_fast(c2 + bsv[nt][0]) * w2v[nt][0];
                s += tanh_fast(c3 + bsv[nt][1]) * w2v[nt][1];
            }
        }
        __syncthreads();
    }

#pragma unroll
    for (int off = 16; off > 0; off >>= 1)
        s += __shfl_xor_sync(0xffffffffu, s, off);
    if (lane == 0) wsum[warp] = s;
    __syncthreads();
    if (tid < 2) {
        float tot = wsum[tid * 4] + wsum[tid * 4 + 1]
                  + wsum[tid * 4 + 2] + wsum[tid * 4 + 3];
        atomicAdd(&g_w[2 * t + tid], tot);
    }
}

// ---------------- K6: gather + bias/ELU + beta + GEMM + ReLU + LN ------------
__global__ void __launch_bounds__(256) k_final(
    const int* __restrict__ user_idx, const int* __restrict__ item_idx,
    const int* __restrict__ neg_idx,
    const float* __restrict__ u_gb, const float* __restrict__ i_gb,
    const float* __restrict__ userW, const float* __restrict__ userb,
    const float* __restrict__ itemW, const float* __restrict__ itemb,
    const float* __restrict__ ln_g, const float* __restrict__ ln_b,
    float* __restrict__ out)
{
    __shared__ float Ws[4096];
    __shared__ float bs[64], gs[64], lbs[64];
    __shared__ float gb0[64], gb1[64];
    __shared__ float embs[4][64];
    __shared__ float red[4][2];

    int tid = threadIdx.x;
    int tx = tid & 63, ty = tid >> 6;
    int r0 = blockIdx.x * 4;
    bool isUser = (r0 < BB);
    const float* W    = isUser ? userW : itemW;
    const float* bias = isUser ? userb : itemb;
    const float* gbm  = isUser ? u_gb : i_gb;

    for (int i = tid; i < 4096; i += 256) Ws[i] = W[i];
    if (tid < 64) {
        bs[tid] = bias[tid]; gs[tid] = ln_g[tid]; lbs[tid] = ln_b[tid];
        gb0[tid] = gbm[tid]; gb1[tid] = gbm[64 + tid];
    }

    int r = r0 + ty;
    int type, idx;
    if (r < BB)            { type = 0; idx = user_idx[r]; }
    else if (r < 2 * BB)   { type = 1; idx = item_idx[r - BB]; }
    else                   { type = 1; idx = neg_idx[r - 2 * BB]; }

    float w0 = g_w[2 * type] * (1.0f / NN);
    float w1 = g_w[2 * type + 1] * (1.0f / NN);
    float mx = fmaxf(w0, w1);
    float e0 = __expf(w0 - mx), e1 = __expf(w1 - mx);
    float binv = 1.0f / (e0 + e1);
    float b0 = e0 * binv, b1 = e1 * binv;

    __syncthreads();
    float zr0 = __half2float(g_z_h[2 * type][(size_t)idx * 64 + tx]) + gb0[tx];
    float zr1 = __half2float(g_z_h[2 * type + 1][(size_t)idx * 64 + tx]) + gb1[tx];
    float emb = b0 * elu_fast(zr0) + b1 * elu_fast(zr1);
    embs[ty][tx] = emb;
    __syncthreads();

    float y = bs[tx];
#pragma unroll 16
    for (int k = 0; k < 64; k++) y += embs[ty][k] * Ws[k * 64 + tx];
    y = fmaxf(y, 0.0f);

    float s = y;
#pragma unroll
    for (int off = 16; off > 0; off >>= 1) s += __shfl_xor_sync(0xffffffffu, s, off);
    int half = tx >> 5;
    if ((tx & 31) == 0) red[ty][half] = s;
    __syncthreads();
    float mu = (red[ty][0] + red[ty][1]) * (1.0f / 64.0f);
    float dv = y - mu;
    float s2 = dv * dv;
#pragma unroll
    for (int off = 16; off > 0; off >>= 1) s2 += __shfl_xor_sync(0xffffffffu, s2, off);
    __syncthreads();
    if ((tx & 31) == 0) red[ty][half] = s2;
    __syncthreads();
    float var = (red[ty][0] + red[ty][1]) * (1.0f / 64.0f);
    float o = gs[tx] * dv * rsqrtf(var + 1e-5f) + lbs[tx];
    out[(size_t)r * 64 + tx] = o;
}

// ---------------- host ------------------------------------------------------
extern "C" void kernel_launch(void* const* d_in, const int* in_sizes, int n_in,
                              void* d_out, int out_size)
{
    const int*   user_idx  = (const int*)d_in[0];
    const int*   item_idx  = (const int*)d_in[1];
    const int*   neg_idx   = (const int*)d_in[2];
    const float* user_feat = (const float*)d_in[3];
    const float* item_feat = (const float*)d_in[4];
    const int*   u_src = (const int*)d_in[5];
    const int*   u_dst = (const int*)d_in[6];
    const int*   i_src = (const int*)d_in[7];
    const int*   i_dst = (const int*)d_in[8];
    const float* u_W  = (const float*)d_in[9];
    const float* u_al = (const float*)d_in[10];
    const float* u_ar = (const float*)d_in[11];
    const float* u_b  = (const float*)d_in[12];
    const float* i_W  = (const float*)d_in[13];
    const float* i_al = (const float*)d_in[14];
    const float* i_ar = (const float*)d_in[15];
    const float* i_b  = (const float*)d_in[16];
    const float* u_saW1 = (const float*)d_in[17];
    const float* u_sab1 = (const float*)d_in[18];
    const float* u_saW2 = (const float*)d_in[19];
    const float* i_saW1 = (const float*)d_in[20];
    const float* i_sab1 = (const float*)d_in[21];
    const float* i_saW2 = (const float*)d_in[22];
    const float* userW = (const float*)d_in[23];
    const float* userb = (const float*)d_in[24];
    const float* itemW = (const float*)d_in[25];
    const float* itemb = (const float*)d_in[26];
    const float* ln_g  = (const float*)d_in[27];
    const float* ln_b  = (const float*)d_in[28];
    float* out = (float*)d_out;

    cudaFuncSetAttribute(k_fused1,
                         cudaFuncAttributeMaxDynamicSharedMemorySize, K1F_SMEM);

    dim3 gridF(NGB + 2 * NHB, 2);                // 2736 x type
    dim3 gridS(NBLK, 4);                         // 391 x slot
    dim3 gridE((EE + 255) / 256, 2, 2);          // 1954 x m x type
    dim3 gridG((NN * 8 + 255) / 256, 4);         // 3125 x slot

    k_fused1<<<gridF, 256, K1F_SMEM>>>(user_feat, item_feat, u_W, i_W,
                                       u_al, i_al, u_ar, i_ar, u_dst, i_dst);
    k_scan<<<gridS, 256>>>();
    k_scatter<<<gridE, 256>>>(u_src, u_dst, i_src, i_dst);
    k_aggr<<<gridG, 256>>>();

    dim3 semGrid(256, 2);
    k_sem_mma<<<semGrid, 256>>>(u_saW1, u_sab1, u_saW2, u_b,
                                i_saW1, i_sab1, i_saW2, i_b);
    k_final<<<(3 * BB) / 4, 256>>>(user_idx, item_idx, neg_idx, u_b, i_b,
                                   userW, userb, itemW, itemb, ln_g, ln_b, out);
}